// round 1
// baseline (speedup 1.0000x reference)
#include <cuda_runtime.h>

// ---------------------------------------------------------------------------
// TensorTrainProjection: out[T, J] = X[T, D] @ W[D, J]
// where W is the dense 2048x2048 matrix obtained by contracting the 9 TT
// cores. Building W costs ~1.4G MACs (tiny); the GEMM is 68.7 GFLOP.
//
// W construction (matches reference einsum exactly):
//   S0[a0, b0, r] = p0[a0, b0, 0, r]                       (8, 8, 16)
//   S_k[(d*2+a), (j*2+b), r'] = sum_l S_{k-1}[d, j, l] * G_k[a, b, l, r']
//     with G_k = p_k for k=1..6,  G_7[a,b,l,r] = p7[a,b,r,l] (swapped bonds),
//     and final core p8 (2,2,16,1) producing W[(d*2+a), (j*2+b)].
// ---------------------------------------------------------------------------

static __device__ float g_Sa[16u * 1024u * 1024u];  // ping (max 64 MB state)
static __device__ float g_Sb[16u * 1024u * 1024u];  // pong
static __device__ float g_W[2048u * 2048u];         // final dense operator

// One contraction step. Each thread owns one (d, a, j, b) and produces RKo
// consecutive outputs (r'). Core tensor (<= 1024 floats) staged in smem.
__global__ void tt_step(const float* __restrict__ S, const float* __restrict__ core,
                        float* __restrict__ out, int D, int J, int TK, int BK,
                        int RKo, int trans)
{
    __shared__ float cs[1024];
    int csz = TK * BK * 16 * RKo;
    for (int i = threadIdx.x; i < csz; i += blockDim.x) cs[i] = core[i];
    __syncthreads();

    int idx = blockIdx.x * blockDim.x + threadIdx.x;
    int total = D * TK * J * BK;
    if (idx >= total) return;

    int b  = idx % BK; int t1 = idx / BK;
    int j  = t1 % J;   int t2 = t1 / J;
    int a  = t2 % TK;  int d  = t2 / TK;

    const float* srow = S + ((long)d * J + j) * 16;
    float s[16];
    #pragma unroll
    for (int l = 0; l < 16; ++l) s[l] = srow[l];

    int ab = a * BK + b;
    long obase = ((long)(d * TK + a) * (long)(J * BK) + (j * BK + b)) * RKo;
    for (int r = 0; r < RKo; ++r) {
        float acc = 0.f;
        #pragma unroll
        for (int l = 0; l < 16; ++l) {
            // normal cores: p[a][b][l][r];  core 7 stores [a][b][r][l]
            float cv = trans ? cs[(ab * 16 + r) * 16 + l]
                             : cs[(ab * 16 + l) * RKo + r];
            acc = fmaf(s[l], cv, acc);
        }
        out[obase + r] = acc;
    }
}

// ---------------------------------------------------------------------------
// fp32 SGEMM: C[M,N] = A[M,K] @ B[K,N], row-major, M=8192 N=2048 K=2048.
// BM=BN=128, BK=8, 256 threads, 8x8 register microtile per thread.
// ---------------------------------------------------------------------------
__global__ __launch_bounds__(256, 2)
void sgemm128(const float* __restrict__ A, const float* __restrict__ B,
              float* __restrict__ C, int M, int N, int K)
{
    const int BM = 128, BN = 128, BKd = 8, TM = 8, TN = 8;
    __shared__ float As[BKd][BM];
    __shared__ float Bs[BKd][BN];

    int bx = blockIdx.x;   // N tile
    int by = blockIdx.y;   // M tile
    int tid = threadIdx.x;
    int tx = tid % 16;     // column group
    int ty = tid / 16;     // row group

    // global-load assignments (float4)
    int aRow = tid >> 1;          // 0..127
    int aCol = (tid & 1) * 4;     // 0 or 4
    int bRow = tid >> 5;          // 0..7
    int bCol = (tid & 31) * 4;    // 0..124

    const float* Ab = A + (long)by * BM * K;
    const float* Bb = B + (long)bx * BN;

    float acc[TM][TN];
    #pragma unroll
    for (int i = 0; i < TM; ++i)
        #pragma unroll
        for (int j = 0; j < TN; ++j) acc[i][j] = 0.f;

    for (int k0 = 0; k0 < K; k0 += BKd) {
        float4 av = *(const float4*)(Ab + (long)aRow * K + k0 + aCol);
        As[aCol + 0][aRow] = av.x;
        As[aCol + 1][aRow] = av.y;
        As[aCol + 2][aRow] = av.z;
        As[aCol + 3][aRow] = av.w;
        float4 bv = *(const float4*)(Bb + (long)(k0 + bRow) * N + bCol);
        *(float4*)&Bs[bRow][bCol] = bv;
        __syncthreads();

        #pragma unroll
        for (int k = 0; k < BKd; ++k) {
            float ra[TM], rb[TN];
            #pragma unroll
            for (int i = 0; i < TM; ++i) ra[i] = As[k][ty * TM + i];
            #pragma unroll
            for (int j = 0; j < TN; ++j) rb[j] = Bs[k][tx * TN + j];
            #pragma unroll
            for (int i = 0; i < TM; ++i)
                #pragma unroll
                for (int j = 0; j < TN; ++j)
                    acc[i][j] = fmaf(ra[i], rb[j], acc[i][j]);
        }
        __syncthreads();
    }

    float* Cb = C + (long)(by * BM + ty * TM) * N + bx * BN + tx * TN;
    #pragma unroll
    for (int i = 0; i < TM; ++i) {
        #pragma unroll
        for (int j = 0; j < TN; j += 4) {
            *(float4*)(Cb + (long)i * N + j) =
                make_float4(acc[i][j], acc[i][j + 1], acc[i][j + 2], acc[i][j + 3]);
        }
    }
}

extern "C" void kernel_launch(void* const* d_in, const int* in_sizes, int n_in,
                              void* d_out, int out_size)
{
    (void)in_sizes; (void)n_in; (void)out_size;
    const float* x = (const float*)d_in[0];
    const float* p[9];
    for (int i = 0; i < 9; ++i) p[i] = (const float*)d_in[1 + i];

    float *Sa, *Sb, *W;
    cudaGetSymbolAddress((void**)&Sa, g_Sa);
    cudaGetSymbolAddress((void**)&Sb, g_Sb);
    cudaGetSymbolAddress((void**)&W,  g_W);

    // --- build W from the TT cores ---
    const float* cur = p[0];     // S0 = p0 viewed as [8, 8, 16]
    int D = 8, J = 8;
    float* bufs[2] = {Sa, Sb};
    int which = 0;
    for (int k = 1; k <= 7; ++k) {
        float* outb = bufs[which];
        int total = D * 2 * J * 2;
        int blocks = (total + 255) / 256;
        tt_step<<<blocks, 256>>>(cur, p[k], outb, D, J, 2, 2, 16, (k == 7) ? 1 : 0);
        cur = outb;
        which ^= 1;
        D *= 2; J *= 2;
    }
    {   // final core (2,2,16,1) -> W[2048, 2048]
        int total = D * 2 * J * 2;               // 4,194,304
        int blocks = (total + 255) / 256;
        tt_step<<<blocks, 256>>>(cur, p[8], W, D, J, 2, 2, 1, 0);
    }

    // --- out = X @ W ---
    dim3 grid(2048 / 128, 8192 / 128);
    sgemm128<<<grid, 256>>>(x, W, (float*)d_out, 8192, 2048, 2048);
}

// round 3
// speedup vs baseline: 3.1672x; 3.1672x over previous
#include <cuda_runtime.h>
#include <cuda_bf16.h>
#include <cstdint>

// ===========================================================================
// TensorTrainProjection via dense operator:
//   W[d, j] = TT-contraction of 9 cores (2048 x 2048)
//   out[T, J] = X[T, D] @ W            (T = 8192, fp32)
//
// Round-3: bf16 mma.sync (m16n8k16) GEMM with 3-term fp32 emulation
//   C = Xhi@Whi^T + Xhi@Wlo^T + Xlo@Whi^T   (K = 3 x 2048 = 6144)
// (tcgen05 is 'a'-feature-gated and the harness PTX target is plain sm_103,
//  so we use the base-ISA tensor path: cp.async + ldmatrix + mma.sync.)
// W built as L(cores0-4)[128,128,16] x R(cores5-8)[16,16,16].
// GEMM operands stored pre-swizzled (SW128) in 16KB K-major tiles so the
// GEMM's cp.async is a byte-identical 16B-chunk copy.
// ===========================================================================

__device__ __forceinline__ uint32_t smem_u32(const void* p) {
    uint32_t a;
    asm("{ .reg .u64 t; cvta.to.shared.u64 t, %1; cvt.u32.u64 %0, t; }" : "=r"(a) : "l"(p));
    return a;
}
__device__ __forceinline__ uint32_t swz(uint32_t o) { return o ^ ((o >> 3) & 0x70); }

__device__ __forceinline__ void cp16(uint32_t dst, const void* src) {
    asm volatile("cp.async.cg.shared.global [%0], [%1], 16;" :: "r"(dst), "l"(src) : "memory");
}
__device__ __forceinline__ void cp_commit() { asm volatile("cp.async.commit_group;" ::: "memory"); }
template <int N>
__device__ __forceinline__ void cp_wait() { asm volatile("cp.async.wait_group %0;" :: "n"(N) : "memory"); }

__device__ __forceinline__ void ldsm_x4(uint32_t* r, uint32_t addr) {
    asm volatile("ldmatrix.sync.aligned.m8n8.x4.shared.b16 {%0,%1,%2,%3}, [%4];"
                 : "=r"(r[0]), "=r"(r[1]), "=r"(r[2]), "=r"(r[3]) : "r"(addr));
}
__device__ __forceinline__ void ldsm_x2(uint32_t* r, uint32_t addr) {
    asm volatile("ldmatrix.sync.aligned.m8n8.x2.shared.b16 {%0,%1}, [%2];"
                 : "=r"(r[0]), "=r"(r[1]) : "r"(addr));
}
__device__ __forceinline__ void mma16816(float* c, const uint32_t* a, const uint32_t* b) {
    asm volatile(
        "mma.sync.aligned.m16n8k16.row.col.f32.bf16.bf16.f32 "
        "{%0,%1,%2,%3}, {%4,%5,%6,%7}, {%8,%9}, {%0,%1,%2,%3};"
        : "+f"(c[0]), "+f"(c[1]), "+f"(c[2]), "+f"(c[3])
        : "r"(a[0]), "r"(a[1]), "r"(a[2]), "r"(a[3]), "r"(b[0]), "r"(b[1]));
}

// ---------------- scratch (static __device__, no allocs) --------------------
static __device__ __align__(16) unsigned char g_Xhi[33554432];  // 64 mt * 32 ch * 16KB
static __device__ __align__(16) unsigned char g_Xlo[33554432];
static __device__ __align__(16) unsigned char g_Whi[8388608];   // 16 nt * 32 ch * 16KB
static __device__ __align__(16) unsigned char g_Wlo[8388608];
static __device__ float g_La[262144];
static __device__ float g_Lb[262144];
static __device__ float g_R[4096];

// ---------------- small TT kernels (verified in round 1) --------------------
__global__ void tt_step(const float* __restrict__ S, const float* __restrict__ core,
                        float* __restrict__ out, int D, int J)
{
    __shared__ float cs[1024];
    for (int i = threadIdx.x; i < 1024; i += blockDim.x) cs[i] = core[i];
    __syncthreads();

    int idx = blockIdx.x * blockDim.x + threadIdx.x;
    int total = D * 2 * J * 2;
    if (idx >= total) return;
    int b = idx & 1; int t1 = idx >> 1;
    int j = t1 % J;  int t2 = t1 / J;
    int a = t2 & 1;  int d = t2 >> 1;

    const float* srow = S + ((long)d * J + j) * 16;
    float s[16];
    #pragma unroll
    for (int l = 0; l < 16; ++l) s[l] = srow[l];
    int ab = a * 2 + b;
    long ob = ((long)(d * 2 + a) * (long)(J * 2) + (j * 2 + b)) * 16;
    #pragma unroll
    for (int r = 0; r < 16; ++r) {
        float acc = 0.f;
        #pragma unroll
        for (int l = 0; l < 16; ++l) acc = fmaf(s[l], cs[(ab * 16 + l) * 16 + r], acc);
        out[ob + r] = acc;
    }
}

// Backward chain cores 8,7,6,5 -> R[r4, dl(16), jl(16)], core7 bond-swapped.
__global__ void build_R(const float* __restrict__ p5, const float* __restrict__ p6,
                        const float* __restrict__ p7, const float* __restrict__ p8,
                        float* __restrict__ Rout)
{
    __shared__ float S[4096], T[4096];
    int t = threadIdx.x;
    if (t < 64) { int l = t >> 2, d = (t >> 1) & 1, j = t & 1; S[l * 4 + d * 2 + j] = p8[(d * 2 + j) * 16 + l]; }
    __syncthreads();
    if (t < 256) {  // core 7: G[a,b,l,r] = p7[a][b][r][l]
        int l = t >> 4, dp = (t >> 2) & 3, jp = t & 3;
        int a = dp >> 1, d = dp & 1, b = jp >> 1, j = jp & 1;
        float acc = 0.f;
        #pragma unroll
        for (int r = 0; r < 16; ++r) acc = fmaf(p7[((a * 2 + b) * 16 + r) * 16 + l], S[r * 4 + d * 2 + j], acc);
        T[l * 16 + dp * 4 + jp] = acc;
    }
    __syncthreads();
    for (int i = t; i < 1024; i += 256) {  // core 6
        int l = i >> 6, dp = (i >> 3) & 7, jp = i & 7;
        int a = dp >> 2, d = dp & 3, b = jp >> 2, j = jp & 3;
        float acc = 0.f;
        #pragma unroll
        for (int r = 0; r < 16; ++r) acc = fmaf(p6[((a * 2 + b) * 16 + l) * 16 + r], T[r * 16 + d * 4 + j], acc);
        S[l * 64 + dp * 8 + jp] = acc;
    }
    __syncthreads();
    for (int i = t; i < 4096; i += 256) {  // core 5
        int l = i >> 8, dp = (i >> 4) & 15, jp = i & 15;
        int a = dp >> 3, d = dp & 7, b = jp >> 3, j = jp & 7;
        float acc = 0.f;
        #pragma unroll
        for (int r = 0; r < 16; ++r) acc = fmaf(p5[((a * 2 + b) * 16 + l) * 16 + r], S[r * 64 + d * 8 + j], acc);
        Rout[i] = acc;
    }
}

// W^T combine: Wt[j, d] = sum_r L[d>>4, j>>4, r] * R[r, d&15, j&15]
// -> bf16 hi/lo in pre-swizzled SW128 K-major 16KB tiles (row = j, col = d).
__global__ void combine_W(const float* __restrict__ L, const float* __restrict__ R,
                          unsigned char* __restrict__ Whi, unsigned char* __restrict__ Wlo)
{
    __shared__ float Rs[4096];
    for (int i = threadIdx.x; i < 4096; i += blockDim.x) Rs[i] = R[i];
    __syncthreads();
    int idx = blockIdx.x * blockDim.x + threadIdx.x;   // < 2048*1024
    int j = idx >> 10;
    int d0 = (idx & 1023) << 1;
    int dh = d0 >> 4, dl = d0 & 15, jh = j >> 4, jl = j & 15;
    const float* Lr = L + ((long)(dh << 7) + jh) * 16;
    float w0 = 0.f, w1 = 0.f;
    #pragma unroll
    for (int r = 0; r < 16; ++r) {
        float lv = Lr[r];
        w0 = fmaf(lv, Rs[r * 256 + dl * 16 + jl], w0);
        w1 = fmaf(lv, Rs[r * 256 + (dl + 1) * 16 + jl], w1);
    }
    __nv_bfloat16 h0 = __float2bfloat16(w0), h1 = __float2bfloat16(w1);
    __nv_bfloat16 l0 = __float2bfloat16(w0 - __bfloat162float(h0));
    __nv_bfloat16 l1 = __float2bfloat16(w1 - __bfloat162float(h1));
    uint32_t off = (uint32_t)(((j >> 7) * 32 + (d0 >> 6)) << 14) + swz((j & 127) * 128 + (d0 & 63) * 2);
    *(uint32_t*)(Whi + off) = (uint32_t)__bfloat16_as_ushort(h0) | ((uint32_t)__bfloat16_as_ushort(h1) << 16);
    *(uint32_t*)(Wlo + off) = (uint32_t)__bfloat16_as_ushort(l0) | ((uint32_t)__bfloat16_as_ushort(l1) << 16);
}

// X hi/lo split into pre-swizzled tiles (row = m, col = k).
__global__ void conv_X(const float* __restrict__ x,
                       unsigned char* __restrict__ Xhi, unsigned char* __restrict__ Xlo)
{
    int idx = blockIdx.x * blockDim.x + threadIdx.x;   // < 8192*512
    int m = idx >> 9;
    int k0 = (idx & 511) << 2;
    float4 v = *(const float4*)(x + (size_t)m * 2048 + k0);
    __nv_bfloat16 h0 = __float2bfloat16(v.x), h1 = __float2bfloat16(v.y);
    __nv_bfloat16 h2 = __float2bfloat16(v.z), h3 = __float2bfloat16(v.w);
    __nv_bfloat16 l0 = __float2bfloat16(v.x - __bfloat162float(h0));
    __nv_bfloat16 l1 = __float2bfloat16(v.y - __bfloat162float(h1));
    __nv_bfloat16 l2 = __float2bfloat16(v.z - __bfloat162float(h2));
    __nv_bfloat16 l3 = __float2bfloat16(v.w - __bfloat162float(h3));
    uint32_t off = (uint32_t)(((m >> 7) * 32 + (k0 >> 6)) << 14) + swz((m & 127) * 128 + (k0 & 63) * 2);
    uint2 ph, pl;
    ph.x = (uint32_t)__bfloat16_as_ushort(h0) | ((uint32_t)__bfloat16_as_ushort(h1) << 16);
    ph.y = (uint32_t)__bfloat16_as_ushort(h2) | ((uint32_t)__bfloat16_as_ushort(h3) << 16);
    pl.x = (uint32_t)__bfloat16_as_ushort(l0) | ((uint32_t)__bfloat16_as_ushort(l1) << 16);
    pl.y = (uint32_t)__bfloat16_as_ushort(l2) | ((uint32_t)__bfloat16_as_ushort(l3) << 16);
    *(uint2*)(Xhi + off) = ph;
    *(uint2*)(Xlo + off) = pl;
}

// ---------------- bf16 mma.sync GEMM ----------------------------------------
// CTA: 128x128 tile of C, K-loop over 96 chunks of 64 (3 segs x 32).
// 256 threads = 8 warps (2m x 4n), warp tile 64x32, 3-stage cp.async pipeline.
static constexpr int GSTAGES = 3;
static constexpr int STAGE_BYTES = 32768;  // 16KB A + 16KB B
static constexpr uint32_t GEMM_SMEM = GSTAGES * STAGE_BYTES;

struct SegPtrs { const unsigned char *a, *b; };

__device__ __forceinline__ void issue_stage(uint32_t sb, int buf, int ck, int tid,
                                            const unsigned char* const* Asegs,
                                            const unsigned char* const* Bsegs,
                                            int by, int bx)
{
    int seg = ck >> 5, c = ck & 31;
    const unsigned char* as = Asegs[seg] + (((size_t)by * 32 + c) << 14) + tid * 16;
    const unsigned char* bs = Bsegs[seg] + (((size_t)bx * 32 + c) << 14) + tid * 16;
    uint32_t dst = sb + buf * STAGE_BYTES + tid * 16;
    #pragma unroll
    for (int i = 0; i < 4; ++i) cp16(dst + i * 4096, as + i * 4096);
    #pragma unroll
    for (int i = 0; i < 4; ++i) cp16(dst + 16384 + i * 4096, bs + i * 4096);
}

__global__ void __launch_bounds__(256, 2)
tt_gemm(const unsigned char* __restrict__ Ahi, const unsigned char* __restrict__ Alo,
        const unsigned char* __restrict__ Bhi, const unsigned char* __restrict__ Blo,
        float* __restrict__ out)
{
    extern __shared__ unsigned char smem[];
    uint32_t sb = smem_u32(smem);
    int tid = threadIdx.x, wid = tid >> 5, lane = tid & 31;
    int bx = blockIdx.x, by = blockIdx.y;

    const unsigned char* Asegs[3] = {Ahi, Ahi, Alo};
    const unsigned char* Bsegs[3] = {Bhi, Blo, Bhi};

    // warp layout: wm in {0,64}, wn in {0,32,64,96}
    int wm = (wid & 1) * 64;
    int wn = (wid >> 1) * 32;
    // ldmatrix lane addressing (within tile; SW128 swizzle applied per access)
    int arow = wm + (lane & 15);
    int akb  = (lane >> 4) * 16;
    int brow = wn + (lane & 7);
    int bkb  = ((lane >> 3) & 1) * 16;

    float acc[4][4][4];
    #pragma unroll
    for (int mi = 0; mi < 4; ++mi)
        #pragma unroll
        for (int ni = 0; ni < 4; ++ni)
            #pragma unroll
            for (int q = 0; q < 4; ++q) acc[mi][ni][q] = 0.f;

    // prologue: prefetch stages 0..GSTAGES-2
    #pragma unroll
    for (int s = 0; s < GSTAGES - 1; ++s) {
        issue_stage(sb, s, s, tid, Asegs, Bsegs, by, bx);
        cp_commit();
    }

    for (int it = 0; it < 96; ++it) {
        cp_wait<GSTAGES - 2>();
        __syncthreads();

        int nxt = it + GSTAGES - 1;
        if (nxt < 96) issue_stage(sb, nxt % GSTAGES, nxt, tid, Asegs, Bsegs, by, bx);
        cp_commit();

        uint32_t base = sb + (it % GSTAGES) * STAGE_BYTES;
        #pragma unroll
        for (int ks = 0; ks < 4; ++ks) {
            uint32_t af[4][4], bf[4][2];
            #pragma unroll
            for (int mi = 0; mi < 4; ++mi)
                ldsm_x4(af[mi], base + swz((uint32_t)((arow + mi * 16) * 128 + ks * 32 + akb)));
            #pragma unroll
            for (int ni = 0; ni < 4; ++ni)
                ldsm_x2(bf[ni], base + 16384 + swz((uint32_t)((brow + ni * 8) * 128 + ks * 32 + bkb)));
            #pragma unroll
            for (int mi = 0; mi < 4; ++mi)
                #pragma unroll
                for (int ni = 0; ni < 4; ++ni)
                    mma16816(acc[mi][ni], af[mi], bf[ni]);
        }
    }

    // epilogue
    int m0 = by * 128 + wm + (lane >> 2);
    int n0 = bx * 128 + wn + (lane & 3) * 2;
    #pragma unroll
    for (int mi = 0; mi < 4; ++mi) {
        #pragma unroll
        for (int ni = 0; ni < 4; ++ni) {
            float* p = out + (size_t)(m0 + mi * 16) * 2048 + n0 + ni * 8;
            *(float2*)p = make_float2(acc[mi][ni][0], acc[mi][ni][1]);
            *(float2*)(p + 8 * 2048) = make_float2(acc[mi][ni][2], acc[mi][ni][3]);
        }
    }
}

// ---------------- launch -----------------------------------------------------
extern "C" void kernel_launch(void* const* d_in, const int* in_sizes, int n_in,
                              void* d_out, int out_size)
{
    (void)in_sizes; (void)n_in; (void)out_size;
    const float* x = (const float*)d_in[0];
    const float* p[9];
    for (int i = 0; i < 9; ++i) p[i] = (const float*)d_in[1 + i];

    unsigned char *Xhi, *Xlo, *Whi, *Wlo;
    float *La, *Lb, *R;
    cudaGetSymbolAddress((void**)&Xhi, g_Xhi);
    cudaGetSymbolAddress((void**)&Xlo, g_Xlo);
    cudaGetSymbolAddress((void**)&Whi, g_Whi);
    cudaGetSymbolAddress((void**)&Wlo, g_Wlo);
    cudaGetSymbolAddress((void**)&La, g_La);
    cudaGetSymbolAddress((void**)&Lb, g_Lb);
    cudaGetSymbolAddress((void**)&R, g_R);

    // X split + pre-swizzle
    conv_X<<<16384, 256>>>(x, Xhi, Xlo);

    // L = cores 0..4
    tt_step<<<4, 256>>>(p[0], p[1], La, 8, 8);
    tt_step<<<16, 256>>>(La, p[2], Lb, 16, 16);
    tt_step<<<64, 256>>>(Lb, p[3], La, 32, 32);
    tt_step<<<256, 256>>>(La, p[4], Lb, 64, 64);   // -> [128,128,16] = L

    // R = cores 5..8
    build_R<<<1, 256>>>(p[5], p[6], p[7], p[8], R);

    // W^T hi/lo, pre-swizzled tiles
    combine_W<<<8192, 256>>>(Lb, R, Whi, Wlo);

    // bf16 mma.sync GEMM
    cudaFuncSetAttribute(tt_gemm, cudaFuncAttributeMaxDynamicSharedMemorySize, GEMM_SMEM);
    tt_gemm<<<dim3(16, 64), 256, GEMM_SMEM>>>(Xhi, Xlo, Whi, Wlo, (float*)d_out);
}